// round 1
// baseline (speedup 1.0000x reference)
#include <cuda_runtime.h>
#include <math.h>
#include <stdint.h>

// ---------------- problem constants (fixed shapes) ----------------
#define N_NODES 131072
#define EDIM    64
#define L0      262144          // rel0 idx len (arity 1 -> 262144 tuples)
#define L1      524288          // rel1 idx len (arity 2 -> 262144 tuples)
#define L2      393216          // rel2 idx len (arity 3 -> 131072 tuples)
#define NROWS   (L0 + L1 + L2)  // total message rows = 1179648

// ---------------- scratch (device globals; no cudaMalloc allowed) ----------
__device__ float    g_msg[(size_t)NROWS * EDIM];     // ~302 MB message buffer
__device__ unsigned g_mu [(size_t)N_NODES * EDIM];   // order-preserving-uint max
__device__ float    g_mf [(size_t)N_NODES * EDIM];   // m as float
__device__ float    g_s  [(size_t)N_NODES * EDIM];   // sum of exp
__device__ int      g_idx[NROWS];                    // normalized int32 indices
__device__ int      g_mode;                          // 1 = indices are int32, 0 = int64

// ---------------- helpers ----------------
__device__ __forceinline__ unsigned f2u(float f) {
    unsigned u = __float_as_uint(f);
    return (u & 0x80000000u) ? ~u : (u | 0x80000000u);
}
__device__ __forceinline__ float u2f(unsigned u) {
    u = (u & 0x80000000u) ? (u & 0x7FFFFFFFu) : ~u;
    return __uint_as_float(u);
}
__device__ __forceinline__ float mishf(float x) {
    float sp = (x > 20.0f) ? x : log1pf(expf(x));
    return x * tanhf(sp);
}

// ---------------- 1. index dtype detection ----------------
// If the idx buffer is genuine int64, every odd 32-bit word (high half of
// values < 2^31) is zero. If it's int32 data, odd words are random indices.
__global__ void detect_kernel(const unsigned* __restrict__ p) {
    __shared__ unsigned red[256];
    unsigned v = 0;
    for (int i = threadIdx.x; i < 4096; i += 256) v |= p[2 * i + 1];
    red[threadIdx.x] = v;
    __syncthreads();
    for (int s = 128; s > 0; s >>= 1) {
        if (threadIdx.x < s) red[threadIdx.x] |= red[threadIdx.x + s];
        __syncthreads();
    }
    if (threadIdx.x == 0) g_mode = (red[0] != 0) ? 1 : 0;
}

__global__ void conv_kernel(const void* __restrict__ p, int ofs, int L) {
    int i = blockIdx.x * 256 + threadIdx.x;
    if (i >= L) return;
    int v;
    if (g_mode) v = ((const int*)p)[i];
    else        v = (int)(((const long long*)p)[i]);
    g_idx[ofs + i] = v;
}

// ---------------- 2. init m (as uint key) and s ----------------
__global__ void init_kernel() {
    size_t i = (size_t)blockIdx.x * 256 + threadIdx.x;
    if (i < (size_t)N_NODES * EDIM) {
        g_mu[i] = 0x80000000u;  // f2u(0.0f)
        g_s[i]  = 1e-16f;
    }
}

// positions written by relation 0 start at -inf (include_self=False semantics)
__global__ void mark_kernel() {
    int i = blockIdx.x * 256 + threadIdx.x;     // over L0 * 64
    if (i >= L0 * EDIM) return;
    int row  = i >> 6;
    int e    = i & 63;
    int node = g_idx[row];
    g_mu[(size_t)node * EDIM + e] = 0x007FFFFFu;  // f2u(-inf)
}

// ---------------- 3. per-relation fused gather + MLP + scatter-max ----------
// blockDim.x == D (one thread per column), R tuples per block.
template <int D, int A, int R>
__global__ void msg_kernel(const float* __restrict__ emb,
                           const float* __restrict__ rw, const float* __restrict__ rb,
                           const float* __restrict__ ow, const float* __restrict__ ob,
                           int idx_ofs /* also the message-row offset */) {
    __shared__ float xs[R][D];
    __shared__ float zs[R][D];
    const int c  = threadIdx.x;          // column 0..D-1
    const int j  = c >> 6;               // which index within tuple
    const int e  = c & 63;
    const int t0 = blockIdx.x * R;

    int node[R];
#pragma unroll
    for (int r = 0; r < R; ++r) {
        node[r] = g_idx[idx_ofs + (t0 + r) * A + j];
        xs[r][c] = emb[(size_t)node[r] * EDIM + e];
    }
    __syncthreads();

    float acc[R];
    // ---- h = x @ rw + rb ----
#pragma unroll
    for (int r = 0; r < R; ++r) acc[r] = rb[c];
    for (int k = 0; k < D; k += 4) {
        float w0 = rw[(k + 0) * D + c];
        float w1 = rw[(k + 1) * D + c];
        float w2 = rw[(k + 2) * D + c];
        float w3 = rw[(k + 3) * D + c];
#pragma unroll
        for (int r = 0; r < R; ++r) {
            float4 x4 = *reinterpret_cast<const float4*>(&xs[r][k]);
            acc[r] += x4.x * w0 + x4.y * w1 + x4.z * w2 + x4.w * w3;
        }
    }
    // ---- z = x + mish(h) ----
#pragma unroll
    for (int r = 0; r < R; ++r) zs[r][c] = xs[r][c] + mishf(acc[r]);
    __syncthreads();

    // ---- out = z @ ow + ob ----
#pragma unroll
    for (int r = 0; r < R; ++r) acc[r] = ob[c];
    for (int k = 0; k < D; k += 4) {
        float w0 = ow[(k + 0) * D + c];
        float w1 = ow[(k + 1) * D + c];
        float w2 = ow[(k + 2) * D + c];
        float w3 = ow[(k + 3) * D + c];
#pragma unroll
        for (int r = 0; r < R; ++r) {
            float4 z4 = *reinterpret_cast<const float4*>(&zs[r][k]);
            acc[r] += z4.x * w0 + z4.y * w1 + z4.z * w2 + z4.w * w3;
        }
    }

    // ---- store message + scatter-max ----
#pragma unroll
    for (int r = 0; r < R; ++r) {
        size_t mrow = (size_t)(idx_ofs) + (size_t)(t0 + r) * A + j;
        g_msg[mrow * EDIM + e] = acc[r];
        atomicMax(&g_mu[(size_t)node[r] * EDIM + e], f2u(acc[r]));
    }
}

// ---------------- 4. m: uint key -> float ----------------
__global__ void mfin_kernel() {
    size_t i = (size_t)blockIdx.x * 256 + threadIdx.x;
    if (i < (size_t)N_NODES * EDIM) g_mf[i] = u2f(g_mu[i]);
}

// ---------------- 5. scatter sum of exp(12*(msg - m)) ----------------
__global__ void expsum_kernel() {
    size_t i = (size_t)blockIdx.x * 256 + threadIdx.x;
    if (i >= (size_t)NROWS * EDIM) return;
    int row  = (int)(i >> 6);
    int e    = (int)(i & 63);
    int node = g_idx[row];
    size_t o = (size_t)node * EDIM + e;
    float v  = expf(12.0f * (g_msg[i] - g_mf[o]));
    atomicAdd(&g_s[o], v);
}

// ---------------- 6. node update MLP: [max_msg | emb] (128) -> 64 ----------
template <int R>
__global__ void update_kernel(const float* __restrict__ emb,
                              const float* __restrict__ rw, const float* __restrict__ rb,
                              const float* __restrict__ ow, const float* __restrict__ ob,
                              float* __restrict__ out) {
    __shared__ float xs[R][128];
    __shared__ float zs[R][128];
    const int c  = threadIdx.x;     // 0..127
    const int n0 = blockIdx.x * R;

#pragma unroll
    for (int r = 0; r < R; ++r) {
        int node = n0 + r;
        float v;
        if (c < 64) {
            size_t o = (size_t)node * EDIM + c;
            v = logf(g_s[o]) * (1.0f / 12.0f) + g_mf[o];
        } else {
            v = emb[(size_t)node * EDIM + (c - 64)];
        }
        xs[r][c] = v;
    }
    __syncthreads();

    float acc[R];
#pragma unroll
    for (int r = 0; r < R; ++r) acc[r] = rb[c];
    for (int k = 0; k < 128; k += 4) {
        float w0 = rw[(k + 0) * 128 + c];
        float w1 = rw[(k + 1) * 128 + c];
        float w2 = rw[(k + 2) * 128 + c];
        float w3 = rw[(k + 3) * 128 + c];
#pragma unroll
        for (int r = 0; r < R; ++r) {
            float4 x4 = *reinterpret_cast<const float4*>(&xs[r][k]);
            acc[r] += x4.x * w0 + x4.y * w1 + x4.z * w2 + x4.w * w3;
        }
    }
#pragma unroll
    for (int r = 0; r < R; ++r) zs[r][c] = xs[r][c] + mishf(acc[r]);
    __syncthreads();

    // out: 64 columns, 128 threads -> each thread does R/2 (row,col) dot products
    for (int i = c; i < R * 64; i += 128) {
        int r  = i >> 6;
        int cc = i & 63;
        float a = ob[cc];
        for (int k = 0; k < 128; k += 4) {
            float4 z4 = *reinterpret_cast<const float4*>(&zs[r][k]);
            a += z4.x * ow[(k + 0) * 64 + cc] + z4.y * ow[(k + 1) * 64 + cc]
               + z4.z * ow[(k + 2) * 64 + cc] + z4.w * ow[(k + 3) * 64 + cc];
        }
        out[(size_t)(n0 + r) * EDIM + cc] = a;
    }
}

// ---------------- launcher ----------------
extern "C" void kernel_launch(void* const* d_in, const int* in_sizes, int n_in,
                              void* d_out, int out_size) {
    const float* emb = (const float*)d_in[0];
    const void*  i0  = d_in[1];
    const void*  i1  = d_in[2];
    const void*  i2  = d_in[3];
    const float* r0rw = (const float*)d_in[4];
    const float* r0rb = (const float*)d_in[5];
    const float* r0ow = (const float*)d_in[6];
    const float* r0ob = (const float*)d_in[7];
    const float* r1rw = (const float*)d_in[8];
    const float* r1rb = (const float*)d_in[9];
    const float* r1ow = (const float*)d_in[10];
    const float* r1ob = (const float*)d_in[11];
    const float* r2rw = (const float*)d_in[12];
    const float* r2rb = (const float*)d_in[13];
    const float* r2ow = (const float*)d_in[14];
    const float* r2ob = (const float*)d_in[15];
    const float* urw  = (const float*)d_in[16];
    const float* urb  = (const float*)d_in[17];
    const float* uow  = (const float*)d_in[18];
    const float* uob  = (const float*)d_in[19];
    float* out = (float*)d_out;

    // 1. index dtype detect + normalize to int32
    detect_kernel<<<1, 256>>>((const unsigned*)i0);
    conv_kernel<<<(L0 + 255) / 256, 256>>>(i0, 0, L0);
    conv_kernel<<<(L1 + 255) / 256, 256>>>(i1, L0, L1);
    conv_kernel<<<(L2 + 255) / 256, 256>>>(i2, L0 + L1, L2);

    // 2. init m/s, mark rel0-written rows with -inf
    const size_t NE = (size_t)N_NODES * EDIM;
    init_kernel<<<(unsigned)((NE + 255) / 256), 256>>>();
    mark_kernel<<<(L0 * EDIM + 255) / 256, 256>>>();

    // 3. per-relation messages + scatter max
    msg_kernel< 64, 1, 16><<<(L0 / 1) / 16,  64>>>(emb, r0rw, r0rb, r0ow, r0ob, 0);
    msg_kernel<128, 2, 16><<<(L1 / 2) / 16, 128>>>(emb, r1rw, r1rb, r1ow, r1ob, L0);
    msg_kernel<192, 3, 16><<<(L2 / 3) / 16, 192>>>(emb, r2rw, r2rb, r2ow, r2ob, L0 + L1);

    // 4. finalize m, 5. scatter exp-sum
    mfin_kernel<<<(unsigned)((NE + 255) / 256), 256>>>();
    const size_t ME = (size_t)NROWS * EDIM;
    expsum_kernel<<<(unsigned)((ME + 255) / 256), 256>>>();

    // 6. node update
    update_kernel<16><<<N_NODES / 16, 128>>>(emb, urw, urb, uow, uob, out);
}

// round 2
// speedup vs baseline: 1.1058x; 1.1058x over previous
#include <cuda_runtime.h>
#include <math.h>
#include <stdint.h>

// ---------------- problem constants (fixed shapes) ----------------
#define N_NODES 131072
#define EDIM    64
#define L0      262144          // rel0 idx len (arity 1 -> 262144 tuples)
#define L1      524288          // rel1 idx len (arity 2 -> 262144 tuples)
#define L2      393216          // rel2 idx len (arity 3 -> 131072 tuples)
#define NROWS   (L0 + L1 + L2)  // total message rows = 1179648

// ---------------- scratch (device globals; no cudaMalloc allowed) ----------
__device__ float    g_msg[(size_t)NROWS * EDIM];     // ~302 MB message buffer
__device__ unsigned g_mu [(size_t)N_NODES * EDIM];   // order-preserving-uint max
__device__ float    g_mf [(size_t)N_NODES * EDIM];   // m as float
__device__ float    g_s  [(size_t)N_NODES * EDIM];   // sum of exp
__device__ int      g_idx[NROWS];                    // normalized int32 indices
__device__ int      g_mode;                          // 1 = indices are int32, 0 = int64

// ---------------- helpers ----------------
__device__ __forceinline__ unsigned f2u(float f) {
    unsigned u = __float_as_uint(f);
    return (u & 0x80000000u) ? ~u : (u | 0x80000000u);
}
__device__ __forceinline__ float u2f(unsigned u) {
    u = (u & 0x80000000u) ? (u & 0x7FFFFFFFu) : ~u;
    return __uint_as_float(u);
}
__device__ __forceinline__ float mishf(float x) {
    float sp = (x > 20.0f) ? x : log1pf(expf(x));
    return x * tanhf(sp);
}

// ---- packed f32x2 FMA (ptxas never emits FFMA2 from C++; PTX-only) ----
typedef unsigned long long ull;
__device__ __forceinline__ ull dup2(float w) {
    ull d;
    asm("mov.b64 %0, {%1, %1};" : "=l"(d) : "f"(w));
    return d;
}
__device__ __forceinline__ void fma2(ull& acc, ull x, ull w) {
    asm("fma.rn.f32x2 %0, %1, %2, %3;" : "=l"(acc) : "l"(x), "l"(w), "l"(acc));
}
__device__ __forceinline__ void unpack2(ull v, float& lo, float& hi) {
    asm("mov.b64 {%0, %1}, %2;" : "=f"(lo), "=f"(hi) : "l"(v));
}

// ---------------- 1. index dtype detection ----------------
// If the idx buffer is genuine int64, every odd 32-bit word (values < 2^31)
// is zero. If it's int32 data, odd words are random indices.
__global__ void detect_kernel(const unsigned* __restrict__ p) {
    __shared__ unsigned red[256];
    unsigned v = 0;
    for (int i = threadIdx.x; i < 4096; i += 256) v |= p[2 * i + 1];
    red[threadIdx.x] = v;
    __syncthreads();
    for (int s = 128; s > 0; s >>= 1) {
        if (threadIdx.x < s) red[threadIdx.x] |= red[threadIdx.x + s];
        __syncthreads();
    }
    if (threadIdx.x == 0) g_mode = (red[0] != 0) ? 1 : 0;
}

__global__ void conv_kernel(const void* __restrict__ p, int ofs, int L) {
    int i = blockIdx.x * 256 + threadIdx.x;
    if (i >= L) return;
    int v;
    if (g_mode) v = ((const int*)p)[i];
    else        v = (int)(((const long long*)p)[i]);
    g_idx[ofs + i] = v;
}

// ---------------- 2. init m (as uint key) and s ----------------
__global__ void init_kernel() {
    size_t i = (size_t)blockIdx.x * 256 + threadIdx.x;
    if (i < (size_t)N_NODES * EDIM) {
        g_mu[i] = 0x80000000u;  // f2u(0.0f)
        g_s[i]  = 1e-16f;
    }
}

// positions written by relation 0 start at -inf (include_self=False semantics)
__global__ void mark_kernel() {
    int i = blockIdx.x * 256 + threadIdx.x;     // over L0 * 64
    if (i >= L0 * EDIM) return;
    int row  = i >> 6;
    int e    = i & 63;
    int node = g_idx[row];
    g_mu[(size_t)node * EDIM + e] = 0x007FFFFFu;  // f2u(-inf)
}

// ---------------- 3. per-relation fused gather + MLP + scatter-max ----------
// blockDim.x == D (one thread per column), R tuples per block.
// Row pairs are packed into f32x2 lanes: shared layout xs[p][2k+h] holds
// element k of rows (2p, 2p+1). All LDS are lane-uniform (broadcast).
template <int D, int A, int R>
__global__ void msg_kernel(const float* __restrict__ emb,
                           const float* __restrict__ rw, const float* __restrict__ rb,
                           const float* __restrict__ ow, const float* __restrict__ ob,
                           int idx_ofs /* also the message-row offset */) {
    constexpr int R2 = R / 2;
    __shared__ __align__(16) float xs[R2][2 * D];
    __shared__ __align__(16) float zs[R2][2 * D];
    const int c  = threadIdx.x;          // column 0..D-1
    const int j  = c >> 6;               // which index within tuple
    const int e  = c & 63;
    const int t0 = blockIdx.x * R;

    int   node[R];
    float xreg[R];
#pragma unroll
    for (int r = 0; r < R; ++r) {
        node[r] = g_idx[idx_ofs + (t0 + r) * A + j];
        xreg[r] = emb[(size_t)node[r] * EDIM + e];
        xs[r >> 1][2 * c + (r & 1)] = xreg[r];
    }
    __syncthreads();

    ull acc[R2];
    // ---- h = x @ rw + rb ----
#pragma unroll
    for (int p = 0; p < R2; ++p) acc[p] = dup2(rb[c]);
#pragma unroll 4
    for (int k = 0; k < D; k += 2) {
        ull w0 = dup2(rw[(k + 0) * D + c]);
        ull w1 = dup2(rw[(k + 1) * D + c]);
#pragma unroll
        for (int p = 0; p < R2; ++p) {
            ulonglong2 x2 = *reinterpret_cast<const ulonglong2*>(&xs[p][2 * k]);
            fma2(acc[p], x2.x, w0);
            fma2(acc[p], x2.y, w1);
        }
    }
    // ---- z = x + mish(h) ----
#pragma unroll
    for (int p = 0; p < R2; ++p) {
        float h0, h1;
        unpack2(acc[p], h0, h1);
        zs[p][2 * c + 0] = xreg[2 * p + 0] + mishf(h0);
        zs[p][2 * c + 1] = xreg[2 * p + 1] + mishf(h1);
    }
    __syncthreads();

    // ---- out = z @ ow + ob ----
#pragma unroll
    for (int p = 0; p < R2; ++p) acc[p] = dup2(ob[c]);
#pragma unroll 4
    for (int k = 0; k < D; k += 2) {
        ull w0 = dup2(ow[(k + 0) * D + c]);
        ull w1 = dup2(ow[(k + 1) * D + c]);
#pragma unroll
        for (int p = 0; p < R2; ++p) {
            ulonglong2 z2 = *reinterpret_cast<const ulonglong2*>(&zs[p][2 * k]);
            fma2(acc[p], z2.x, w0);
            fma2(acc[p], z2.y, w1);
        }
    }

    // ---- store message + scatter-max ----
#pragma unroll
    for (int p = 0; p < R2; ++p) {
        float o0, o1;
        unpack2(acc[p], o0, o1);
        int r0 = 2 * p, r1 = 2 * p + 1;
        size_t m0 = (size_t)idx_ofs + (size_t)(t0 + r0) * A + j;
        size_t m1 = (size_t)idx_ofs + (size_t)(t0 + r1) * A + j;
        g_msg[m0 * EDIM + e] = o0;
        g_msg[m1 * EDIM + e] = o1;
        atomicMax(&g_mu[(size_t)node[r0] * EDIM + e], f2u(o0));
        atomicMax(&g_mu[(size_t)node[r1] * EDIM + e], f2u(o1));
    }
}

// ---------------- 4. m: uint key -> float ----------------
__global__ void mfin_kernel() {
    size_t i = (size_t)blockIdx.x * 256 + threadIdx.x;
    if (i < (size_t)N_NODES * EDIM) g_mf[i] = u2f(g_mu[i]);
}

// ---------------- 5. scatter sum of exp(12*(msg - m)) ----------------
__global__ void expsum_kernel() {
    size_t i = (size_t)blockIdx.x * 256 + threadIdx.x;
    if (i >= (size_t)NROWS * EDIM) return;
    int row  = (int)(i >> 6);
    int e    = (int)(i & 63);
    int node = g_idx[row];
    size_t o = (size_t)node * EDIM + e;
    float v  = expf(12.0f * (g_msg[i] - g_mf[o]));
    atomicAdd(&g_s[o], v);
}

// ---------------- 6. node update MLP: [max_msg | emb] (128) -> 64 ----------
template <int R>
__global__ void update_kernel(const float* __restrict__ emb,
                              const float* __restrict__ rw, const float* __restrict__ rb,
                              const float* __restrict__ ow, const float* __restrict__ ob,
                              float* __restrict__ out) {
    constexpr int R2 = R / 2;
    __shared__ __align__(16) float xs[R2][256];
    __shared__ __align__(16) float zs[R2][256];
    const int c  = threadIdx.x;     // 0..127
    const int n0 = blockIdx.x * R;

    float xreg[R];
#pragma unroll
    for (int r = 0; r < R; ++r) {
        int node = n0 + r;
        float v;
        if (c < 64) {
            size_t o = (size_t)node * EDIM + c;
            v = logf(g_s[o]) * (1.0f / 12.0f) + g_mf[o];
        } else {
            v = emb[(size_t)node * EDIM + (c - 64)];
        }
        xreg[r] = v;
        xs[r >> 1][2 * c + (r & 1)] = v;
    }
    __syncthreads();

    ull acc[R2];
#pragma unroll
    for (int p = 0; p < R2; ++p) acc[p] = dup2(rb[c]);
#pragma unroll 4
    for (int k = 0; k < 128; k += 2) {
        ull w0 = dup2(rw[(k + 0) * 128 + c]);
        ull w1 = dup2(rw[(k + 1) * 128 + c]);
#pragma unroll
        for (int p = 0; p < R2; ++p) {
            ulonglong2 x2 = *reinterpret_cast<const ulonglong2*>(&xs[p][2 * k]);
            fma2(acc[p], x2.x, w0);
            fma2(acc[p], x2.y, w1);
        }
    }
#pragma unroll
    for (int p = 0; p < R2; ++p) {
        float h0, h1;
        unpack2(acc[p], h0, h1);
        zs[p][2 * c + 0] = xreg[2 * p + 0] + mishf(h0);
        zs[p][2 * c + 1] = xreg[2 * p + 1] + mishf(h1);
    }
    __syncthreads();

    // out: 64 columns. Thread c handles column cc=c&63 for row-pairs
    // p = (c>>6) + 2*t, t = 0..3  (128 threads x 4 tasks = 8 pairs x 64 cols)
    const int cc = c & 63;
#pragma unroll
    for (int t = 0; t < 4; ++t) {
        int p = (c >> 6) + 2 * t;
        ull a = dup2(ob[cc]);
#pragma unroll 4
        for (int k = 0; k < 128; k += 2) {
            ull w0 = dup2(ow[(k + 0) * 64 + cc]);
            ull w1 = dup2(ow[(k + 1) * 64 + cc]);
            ulonglong2 z2 = *reinterpret_cast<const ulonglong2*>(&zs[p][2 * k]);
            fma2(a, z2.x, w0);
            fma2(a, z2.y, w1);
        }
        float o0, o1;
        unpack2(a, o0, o1);
        out[(size_t)(n0 + 2 * p + 0) * EDIM + cc] = o0;
        out[(size_t)(n0 + 2 * p + 1) * EDIM + cc] = o1;
    }
}

// ---------------- launcher ----------------
extern "C" void kernel_launch(void* const* d_in, const int* in_sizes, int n_in,
                              void* d_out, int out_size) {
    const float* emb = (const float*)d_in[0];
    const void*  i0  = d_in[1];
    const void*  i1  = d_in[2];
    const void*  i2  = d_in[3];
    const float* r0rw = (const float*)d_in[4];
    const float* r0rb = (const float*)d_in[5];
    const float* r0ow = (const float*)d_in[6];
    const float* r0ob = (const float*)d_in[7];
    const float* r1rw = (const float*)d_in[8];
    const float* r1rb = (const float*)d_in[9];
    const float* r1ow = (const float*)d_in[10];
    const float* r1ob = (const float*)d_in[11];
    const float* r2rw = (const float*)d_in[12];
    const float* r2rb = (const float*)d_in[13];
    const float* r2ow = (const float*)d_in[14];
    const float* r2ob = (const float*)d_in[15];
    const float* urw  = (const float*)d_in[16];
    const float* urb  = (const float*)d_in[17];
    const float* uow  = (const float*)d_in[18];
    const float* uob  = (const float*)d_in[19];
    float* out = (float*)d_out;

    // 1. index dtype detect + normalize to int32
    detect_kernel<<<1, 256>>>((const unsigned*)i0);
    conv_kernel<<<(L0 + 255) / 256, 256>>>(i0, 0, L0);
    conv_kernel<<<(L1 + 255) / 256, 256>>>(i1, L0, L1);
    conv_kernel<<<(L2 + 255) / 256, 256>>>(i2, L0 + L1, L2);

    // 2. init m/s, mark rel0-written rows with -inf
    const size_t NE = (size_t)N_NODES * EDIM;
    init_kernel<<<(unsigned)((NE + 255) / 256), 256>>>();
    mark_kernel<<<(L0 * EDIM + 255) / 256, 256>>>();

    // 3. per-relation messages + scatter max
    msg_kernel< 64, 1, 16><<<(L0 / 1) / 16,  64>>>(emb, r0rw, r0rb, r0ow, r0ob, 0);
    msg_kernel<128, 2, 16><<<(L1 / 2) / 16, 128>>>(emb, r1rw, r1rb, r1ow, r1ob, L0);
    msg_kernel<192, 3, 16><<<(L2 / 3) / 16, 192>>>(emb, r2rw, r2rb, r2ow, r2ob, L0 + L1);

    // 4. finalize m, 5. scatter exp-sum
    mfin_kernel<<<(unsigned)((NE + 255) / 256), 256>>>();
    const size_t ME = (size_t)NROWS * EDIM;
    expsum_kernel<<<(unsigned)((ME + 255) / 256), 256>>>();

    // 6. node update
    update_kernel<16><<<N_NODES / 16, 128>>>(emb, urw, urb, uow, uob, out);
}

// round 3
// speedup vs baseline: 1.2267x; 1.1092x over previous
#include <cuda_runtime.h>
#include <math.h>
#include <stdint.h>

// ---------------- problem constants (fixed shapes) ----------------
#define N_NODES 131072
#define EDIM    64
#define L0      262144          // rel0 idx len (arity 1 -> 262144 tuples)
#define L1      524288          // rel1 idx len (arity 2 -> 262144 tuples)
#define L2      393216          // rel2 idx len (arity 3 -> 131072 tuples)
#define NROWS   (L0 + L1 + L2)  // total message rows = 1179648

// ---------------- scratch (device globals; no cudaMalloc allowed) ----------
__device__ float    g_msg[(size_t)NROWS * EDIM];   // sorted-by-node message rows
__device__ float    g_mf [(size_t)N_NODES * EDIM]; // final max_msg per node
__device__ int      g_idx[NROWS];                  // normalized int32 indices
__device__ int      g_pos[NROWS];                  // sorted slot for each row
__device__ int      g_cnt[N_NODES];                // rows per node
__device__ int      g_start[N_NODES];              // exclusive prefix of g_cnt
__device__ int      g_rank[N_NODES];               // running rank counters
__device__ int      g_flag[N_NODES];               // 1 = node written by rel0
__device__ int      g_mode;                        // 1 = int32 indices, 0 = int64

// ---------------- helpers ----------------
__device__ __forceinline__ float mishf(float x) {
    float sp = (x > 20.0f) ? x : log1pf(expf(x));
    return x * tanhf(sp);
}

// ---- packed f32x2 FMA (ptxas never emits FFMA2 from C++; PTX-only) ----
typedef unsigned long long ull;
__device__ __forceinline__ ull dup2(float w) {
    ull d;
    asm("mov.b64 %0, {%1, %1};" : "=l"(d) : "f"(w));
    return d;
}
__device__ __forceinline__ void fma2(ull& acc, ull x, ull w) {
    asm("fma.rn.f32x2 %0, %1, %2, %3;" : "=l"(acc) : "l"(x), "l"(w), "l"(acc));
}
__device__ __forceinline__ void unpack2(ull v, float& lo, float& hi) {
    asm("mov.b64 {%0, %1}, %2;" : "=f"(lo), "=f"(hi) : "l"(v));
}

// ---------------- 1. index dtype detection ----------------
// Genuine int64 (values < 2^31): every odd 32-bit word is zero.
__global__ void detect_kernel(const unsigned* __restrict__ p) {
    __shared__ unsigned red[256];
    unsigned v = 0;
    for (int i = threadIdx.x; i < 4096; i += 256) v |= p[2 * i + 1];
    red[threadIdx.x] = v;
    __syncthreads();
    for (int s = 128; s > 0; s >>= 1) {
        if (threadIdx.x < s) red[threadIdx.x] |= red[threadIdx.x + s];
        __syncthreads();
    }
    if (threadIdx.x == 0) g_mode = (red[0] != 0) ? 1 : 0;
}

// ---------------- 2. normalize all indices to int32; zero counters ---------
__global__ void conv_kernel(const void* __restrict__ p0,
                            const void* __restrict__ p1,
                            const void* __restrict__ p2) {
    int i = blockIdx.x * 256 + threadIdx.x;
    if (i < N_NODES) { g_cnt[i] = 0; g_flag[i] = 0; }
    if (i >= NROWS) return;
    const void* p; int o;
    if      (i < L0)      { p = p0; o = i; }
    else if (i < L0 + L1) { p = p1; o = i - L0; }
    else                  { p = p2; o = i - L0 - L1; }
    int v;
    if (g_mode) v = ((const int*)p)[o];
    else        v = (int)(((const long long*)p)[o]);
    g_idx[i] = v;
}

// ---------------- 3. histogram + rel0 flag ----------------
__global__ void hist_kernel() {
    int i = blockIdx.x * 256 + threadIdx.x;
    if (i >= NROWS) return;
    int node = g_idx[i];
    atomicAdd(&g_cnt[node], 1);
    if (i < L0) g_flag[node] = 1;   // racy identical writes: benign
}

// ---------------- 4. exclusive scan of counts (single block) --------------
__global__ void scan_kernel() {
    __shared__ int partial[1024];
    const int t = threadIdx.x;          // 1024 threads, 128 nodes each
    const int base = t * 128;
    int local[128];
    int sum = 0;
#pragma unroll 8
    for (int k = 0; k < 128; ++k) { local[k] = sum; sum += g_cnt[base + k]; }
    partial[t] = sum;
    __syncthreads();
    // inclusive block scan over partials
    for (int s = 1; s < 1024; s <<= 1) {
        int v = (t >= s) ? partial[t - s] : 0;
        __syncthreads();
        partial[t] += v;
        __syncthreads();
    }
    int ofs = (t == 0) ? 0 : partial[t - 1];
#pragma unroll 8
    for (int k = 0; k < 128; ++k) {
        g_start[base + k] = ofs + local[k];
        g_rank[base + k]  = 0;
    }
}

// ---------------- 5. per-row sorted position ----------------
__global__ void rank_kernel() {
    int i = blockIdx.x * 256 + threadIdx.x;
    if (i >= NROWS) return;
    int node = g_idx[i];
    int r = atomicAdd(&g_rank[node], 1);
    g_pos[i] = g_start[node] + r;
}

// ---------------- 6. per-relation fused gather + MLP + sorted store -------
// blockDim.x == D (one thread per column), R tuples per block.
// Row pairs packed into f32x2 lanes: xs[p][2k+h] = element k of rows (2p,2p+1).
template <int D, int A, int R>
__global__ void msg_kernel(const float* __restrict__ emb,
                           const float* __restrict__ rw, const float* __restrict__ rb,
                           const float* __restrict__ ow, const float* __restrict__ ob,
                           int idx_ofs) {
    constexpr int R2 = R / 2;
    __shared__ __align__(16) float xs[R2][2 * D];
    __shared__ __align__(16) float zs[R2][2 * D];
    const int c  = threadIdx.x;          // column 0..D-1
    const int j  = c >> 6;               // which index within tuple
    const int e  = c & 63;
    const int t0 = blockIdx.x * R;

    float xreg[R];
    int   pos[R];
#pragma unroll
    for (int r = 0; r < R; ++r) {
        int rowid = idx_ofs + (t0 + r) * A + j;
        int node  = g_idx[rowid];
        pos[r]    = g_pos[rowid];
        xreg[r]   = emb[(size_t)node * EDIM + e];
        xs[r >> 1][2 * c + (r & 1)] = xreg[r];
    }
    __syncthreads();

    ull acc[R2];
    // ---- h = x @ rw + rb ----
#pragma unroll
    for (int p = 0; p < R2; ++p) acc[p] = dup2(rb[c]);
#pragma unroll 4
    for (int k = 0; k < D; k += 2) {
        ull w0 = dup2(rw[(k + 0) * D + c]);
        ull w1 = dup2(rw[(k + 1) * D + c]);
#pragma unroll
        for (int p = 0; p < R2; ++p) {
            ulonglong2 x2 = *reinterpret_cast<const ulonglong2*>(&xs[p][2 * k]);
            fma2(acc[p], x2.x, w0);
            fma2(acc[p], x2.y, w1);
        }
    }
    // ---- z = x + mish(h) ----
#pragma unroll
    for (int p = 0; p < R2; ++p) {
        float h0, h1;
        unpack2(acc[p], h0, h1);
        zs[p][2 * c + 0] = xreg[2 * p + 0] + mishf(h0);
        zs[p][2 * c + 1] = xreg[2 * p + 1] + mishf(h1);
    }
    __syncthreads();

    // ---- out = z @ ow + ob ----
#pragma unroll
    for (int p = 0; p < R2; ++p) acc[p] = dup2(ob[c]);
#pragma unroll 4
    for (int k = 0; k < D; k += 2) {
        ull w0 = dup2(ow[(k + 0) * D + c]);
        ull w1 = dup2(ow[(k + 1) * D + c]);
#pragma unroll
        for (int p = 0; p < R2; ++p) {
            ulonglong2 z2 = *reinterpret_cast<const ulonglong2*>(&zs[p][2 * k]);
            fma2(acc[p], z2.x, w0);
            fma2(acc[p], z2.y, w1);
        }
    }

    // ---- store message rows at node-sorted slots (no atomics) ----
#pragma unroll
    for (int p = 0; p < R2; ++p) {
        float o0, o1;
        unpack2(acc[p], o0, o1);
        g_msg[(size_t)pos[2 * p + 0] * EDIM + e] = o0;
        g_msg[(size_t)pos[2 * p + 1] * EDIM + e] = o1;
    }
}

// ---------------- 7. segment reduce: max -> sum exp -> max_msg -------------
// One warp per node; lane handles columns (lane, lane+32).
__global__ void reduce_kernel() {
    int node = (blockIdx.x * blockDim.x + threadIdx.x) >> 5;
    if (node >= N_NODES) return;
    const int lane  = threadIdx.x & 31;
    const int start = g_start[node];
    const int end   = start + g_cnt[node];
    const float base = g_flag[node] ? -INFINITY : 0.0f;

    float m0 = base, m1 = base;
    for (int r = start; r < end; ++r) {
        const float* row = &g_msg[(size_t)r * EDIM];
        m0 = fmaxf(m0, row[lane]);
        m1 = fmaxf(m1, row[lane + 32]);
    }
    float s0 = 1e-16f, s1 = 1e-16f;
    for (int r = start; r < end; ++r) {
        const float* row = &g_msg[(size_t)r * EDIM];
        s0 += expf(12.0f * (row[lane]      - m0));
        s1 += expf(12.0f * (row[lane + 32] - m1));
    }
    size_t o = (size_t)node * EDIM;
    g_mf[o + lane]      = logf(s0) * (1.0f / 12.0f) + m0;
    g_mf[o + lane + 32] = logf(s1) * (1.0f / 12.0f) + m1;
}

// ---------------- 8. node update MLP: [max_msg | emb] (128) -> 64 ---------
template <int R>
__global__ void update_kernel(const float* __restrict__ emb,
                              const float* __restrict__ rw, const float* __restrict__ rb,
                              const float* __restrict__ ow, const float* __restrict__ ob,
                              float* __restrict__ out) {
    constexpr int R2 = R / 2;
    __shared__ __align__(16) float xs[R2][256];
    __shared__ __align__(16) float zs[R2][256];
    const int c  = threadIdx.x;     // 0..127
    const int n0 = blockIdx.x * R;

    float xreg[R];
#pragma unroll
    for (int r = 0; r < R; ++r) {
        int node = n0 + r;
        float v = (c < 64) ? g_mf[(size_t)node * EDIM + c]
                           : emb[(size_t)node * EDIM + (c - 64)];
        xreg[r] = v;
        xs[r >> 1][2 * c + (r & 1)] = v;
    }
    __syncthreads();

    ull acc[R2];
#pragma unroll
    for (int p = 0; p < R2; ++p) acc[p] = dup2(rb[c]);
#pragma unroll 4
    for (int k = 0; k < 128; k += 2) {
        ull w0 = dup2(rw[(k + 0) * 128 + c]);
        ull w1 = dup2(rw[(k + 1) * 128 + c]);
#pragma unroll
        for (int p = 0; p < R2; ++p) {
            ulonglong2 x2 = *reinterpret_cast<const ulonglong2*>(&xs[p][2 * k]);
            fma2(acc[p], x2.x, w0);
            fma2(acc[p], x2.y, w1);
        }
    }
#pragma unroll
    for (int p = 0; p < R2; ++p) {
        float h0, h1;
        unpack2(acc[p], h0, h1);
        zs[p][2 * c + 0] = xreg[2 * p + 0] + mishf(h0);
        zs[p][2 * c + 1] = xreg[2 * p + 1] + mishf(h1);
    }
    __syncthreads();

    const int cc = c & 63;
#pragma unroll
    for (int t = 0; t < 4; ++t) {
        int p = (c >> 6) + 2 * t;
        ull a = dup2(ob[cc]);
#pragma unroll 4
        for (int k = 0; k < 128; k += 2) {
            ull w0 = dup2(ow[(k + 0) * 64 + cc]);
            ull w1 = dup2(ow[(k + 1) * 64 + cc]);
            ulonglong2 z2 = *reinterpret_cast<const ulonglong2*>(&zs[p][2 * k]);
            fma2(a, z2.x, w0);
            fma2(a, z2.y, w1);
        }
        float o0, o1;
        unpack2(a, o0, o1);
        out[(size_t)(n0 + 2 * p + 0) * EDIM + cc] = o0;
        out[(size_t)(n0 + 2 * p + 1) * EDIM + cc] = o1;
    }
}

// ---------------- launcher ----------------
extern "C" void kernel_launch(void* const* d_in, const int* in_sizes, int n_in,
                              void* d_out, int out_size) {
    const float* emb = (const float*)d_in[0];
    const void*  i0  = d_in[1];
    const void*  i1  = d_in[2];
    const void*  i2  = d_in[3];
    const float* r0rw = (const float*)d_in[4];
    const float* r0rb = (const float*)d_in[5];
    const float* r0ow = (const float*)d_in[6];
    const float* r0ob = (const float*)d_in[7];
    const float* r1rw = (const float*)d_in[8];
    const float* r1rb = (const float*)d_in[9];
    const float* r1ow = (const float*)d_in[10];
    const float* r1ob = (const float*)d_in[11];
    const float* r2rw = (const float*)d_in[12];
    const float* r2rb = (const float*)d_in[13];
    const float* r2ow = (const float*)d_in[14];
    const float* r2ob = (const float*)d_in[15];
    const float* urw  = (const float*)d_in[16];
    const float* urb  = (const float*)d_in[17];
    const float* uow  = (const float*)d_in[18];
    const float* uob  = (const float*)d_in[19];
    float* out = (float*)d_out;

    // sort prelude (launches 1-5)
    detect_kernel<<<1, 256>>>((const unsigned*)i0);
    conv_kernel<<<(NROWS + 255) / 256, 256>>>(i0, i1, i2);
    hist_kernel<<<(NROWS + 255) / 256, 256>>>();
    scan_kernel<<<1, 1024>>>();
    rank_kernel<<<(NROWS + 255) / 256, 256>>>();

    // messages (launch 6 = biggest GEMM, lands under ncu -s 5 -c 1)
    msg_kernel<128, 2, 16><<<(L1 / 2) / 16, 128>>>(emb, r1rw, r1rb, r1ow, r1ob, L0);
    msg_kernel< 64, 1, 16><<<(L0 / 1) / 16,  64>>>(emb, r0rw, r0rb, r0ow, r0ob, 0);
    msg_kernel<192, 3, 16><<<(L2 / 3) / 16, 192>>>(emb, r2rw, r2rb, r2ow, r2ob, L0 + L1);

    // segment softmax-reduce, then node update
    reduce_kernel<<<(N_NODES * 32 + 255) / 256, 256>>>();
    update_kernel<16><<<N_NODES / 16, 128>>>(emb, urw, urb, uow, uob, out);
}

// round 4
// speedup vs baseline: 1.3814x; 1.1262x over previous
#include <cuda_runtime.h>
#include <math.h>
#include <stdint.h>

// ---------------- problem constants (fixed shapes) ----------------
#define N_NODES 131072
#define EDIM    64
#define L0      262144          // rel0 idx len (arity 1 -> 262144 tuples)
#define L1      524288          // rel1 idx len (arity 2 -> 262144 tuples)
#define L2      393216          // rel2 idx len (arity 3 -> 131072 tuples)
#define NROWS   (L0 + L1 + L2)  // total message rows = 1179648

#define SCAN_BLOCKS 512         // N_NODES / 256

// ---------------- scratch (device globals; no cudaMalloc allowed) ----------
__device__ float    g_msg[(size_t)NROWS * EDIM];   // sorted-by-node message rows
__device__ float    g_mf [(size_t)N_NODES * EDIM]; // final max_msg per node
__device__ int      g_idx[NROWS];                  // normalized int32 indices
__device__ int      g_pos[NROWS];                  // sorted slot for each row
__device__ int      g_cnt[N_NODES];                // rows per node
__device__ int      g_start[N_NODES];              // exclusive prefix of g_cnt
__device__ int      g_rank[N_NODES];               // running rank counters
__device__ int      g_flag[N_NODES];               // 1 = node written by rel0
__device__ int      g_bsum[SCAN_BLOCKS];           // per-block sums for scan
__device__ int      g_mode;                        // 1 = int32 indices, 0 = int64

// ---------------- helpers ----------------
__device__ __forceinline__ float mishf(float x) {
    float sp = (x > 20.0f) ? x : log1pf(expf(x));
    return x * tanhf(sp);
}

// ---- packed f32x2 FMA (ptxas never emits FFMA2 from C++; PTX-only) ----
typedef unsigned long long ull;
__device__ __forceinline__ ull dup2(float w) {
    ull d;
    asm("mov.b64 %0, {%1, %1};" : "=l"(d) : "f"(w));
    return d;
}
__device__ __forceinline__ void fma2(ull& acc, ull x, ull w) {
    asm("fma.rn.f32x2 %0, %1, %2, %3;" : "=l"(acc) : "l"(x), "l"(w), "l"(acc));
}
__device__ __forceinline__ void unpack2(ull v, float& lo, float& hi) {
    asm("mov.b64 {%0, %1}, %2;" : "=f"(lo), "=f"(hi) : "l"(v));
}

// ---------------- 1. index dtype detection ----------------
// Genuine int64 (values < 2^31): every odd 32-bit word is zero.
__global__ void detect_kernel(const unsigned* __restrict__ p) {
    __shared__ unsigned red[256];
    unsigned v = 0;
    for (int i = threadIdx.x; i < 4096; i += 256) v |= p[2 * i + 1];
    red[threadIdx.x] = v;
    __syncthreads();
    for (int s = 128; s > 0; s >>= 1) {
        if (threadIdx.x < s) red[threadIdx.x] |= red[threadIdx.x + s];
        __syncthreads();
    }
    if (threadIdx.x == 0) g_mode = (red[0] != 0) ? 1 : 0;
}

// ---------------- 2. normalize all indices to int32; zero counters ---------
__global__ void conv_kernel(const void* __restrict__ p0,
                            const void* __restrict__ p1,
                            const void* __restrict__ p2) {
    int i = blockIdx.x * 256 + threadIdx.x;
    if (i < N_NODES) { g_cnt[i] = 0; g_flag[i] = 0; }
    if (i >= NROWS) return;
    const void* p; int o;
    if      (i < L0)      { p = p0; o = i; }
    else if (i < L0 + L1) { p = p1; o = i - L0; }
    else                  { p = p2; o = i - L0 - L1; }
    int v;
    if (g_mode) v = ((const int*)p)[o];
    else        v = (int)(((const long long*)p)[o]);
    g_idx[i] = v;
}

// ---------------- 3. histogram + rel0 flag ----------------
__global__ void hist_kernel() {
    int i = blockIdx.x * 256 + threadIdx.x;
    if (i >= NROWS) return;
    int node = g_idx[i];
    atomicAdd(&g_cnt[node], 1);
    if (i < L0) g_flag[node] = 1;   // racy identical writes: benign
}

// ---------------- 4. hierarchical exclusive scan of g_cnt ----------------
// A: per-block (256 nodes) sum -> g_bsum
__global__ void scanA_kernel() {
    __shared__ int wsum[8];
    const int t = threadIdx.x;
    int v = g_cnt[blockIdx.x * 256 + t];
#pragma unroll
    for (int s = 16; s > 0; s >>= 1) v += __shfl_down_sync(0xffffffffu, v, s);
    if ((t & 31) == 0) wsum[t >> 5] = v;
    __syncthreads();
    if (t < 8) {
        int x = wsum[t];
#pragma unroll
        for (int s = 4; s > 0; s >>= 1) x += __shfl_down_sync(0xffu, x, s);
        if (t == 0) g_bsum[blockIdx.x] = x;
    }
}

// B: exclusive scan of the 512 block sums (single block, 512 threads)
__global__ void scanB_kernel() {
    __shared__ int wsum[16];
    const int t = threadIdx.x;
    const int lane = t & 31, w = t >> 5;
    int v = g_bsum[t];
    int inc = v;
#pragma unroll
    for (int s = 1; s < 32; s <<= 1) {
        int u = __shfl_up_sync(0xffffffffu, inc, s);
        if (lane >= s) inc += u;
    }
    if (lane == 31) wsum[w] = inc;
    __syncthreads();
    if (t < 16) {
        int x = wsum[t];
#pragma unroll
        for (int s = 1; s < 16; s <<= 1) {
            int u = __shfl_up_sync(0xffffu, x, s);
            if (t >= s) x += u;
        }
        wsum[t] = x;
    }
    __syncthreads();
    int wofs = (w == 0) ? 0 : wsum[w - 1];
    g_bsum[t] = wofs + inc - v;     // exclusive
}

// C: final exclusive scan within each block + zero rank
__global__ void scanC_kernel() {
    __shared__ int wsum[8];
    const int t = threadIdx.x;
    const int lane = t & 31, w = t >> 5;
    const int i = blockIdx.x * 256 + t;
    int v = g_cnt[i];
    int inc = v;
#pragma unroll
    for (int s = 1; s < 32; s <<= 1) {
        int u = __shfl_up_sync(0xffffffffu, inc, s);
        if (lane >= s) inc += u;
    }
    if (lane == 31) wsum[w] = inc;
    __syncthreads();
    if (t < 8) {
        int x = wsum[t];
#pragma unroll
        for (int s = 1; s < 8; s <<= 1) {
            int u = __shfl_up_sync(0xffu, x, s);
            if (t >= s) x += u;
        }
        wsum[t] = x;
    }
    __syncthreads();
    int wofs = (w == 0) ? 0 : wsum[w - 1];
    g_start[i] = g_bsum[blockIdx.x] + wofs + inc - v;
    g_rank[i]  = 0;
}

// ---------------- 5. per-row sorted position ----------------
__global__ void rank_kernel() {
    int i = blockIdx.x * 256 + threadIdx.x;
    if (i >= NROWS) return;
    int node = g_idx[i];
    int r = atomicAdd(&g_rank[node], 1);
    g_pos[i] = g_start[node] + r;
}

// ---------------- 6. per-relation fused gather + MLP + sorted store -------
// blockDim.x == D (one thread per column), R tuples per block.
// Row pairs packed into f32x2 lanes: xs[p][2k+h] = element k of rows (2p,2p+1).
template <int D, int A, int R>
__global__ void msg_kernel(const float* __restrict__ emb,
                           const float* __restrict__ rw, const float* __restrict__ rb,
                           const float* __restrict__ ow, const float* __restrict__ ob,
                           int idx_ofs) {
    constexpr int R2 = R / 2;
    __shared__ __align__(16) float xs[R2][2 * D];
    __shared__ __align__(16) float zs[R2][2 * D];
    const int c  = threadIdx.x;          // column 0..D-1
    const int j  = c >> 6;               // which index within tuple
    const int e  = c & 63;
    const int t0 = blockIdx.x * R;

    float xreg[R];
    int   pos[R];
#pragma unroll
    for (int r = 0; r < R; ++r) {
        int rowid = idx_ofs + (t0 + r) * A + j;
        int node  = g_idx[rowid];
        pos[r]    = g_pos[rowid];
        xreg[r]   = emb[(size_t)node * EDIM + e];
        xs[r >> 1][2 * c + (r & 1)] = xreg[r];
    }
    __syncthreads();

    ull acc[R2];
    // ---- h = x @ rw + rb ----
#pragma unroll
    for (int p = 0; p < R2; ++p) acc[p] = dup2(rb[c]);
#pragma unroll 4
    for (int k = 0; k < D; k += 2) {
        ull w0 = dup2(rw[(k + 0) * D + c]);
        ull w1 = dup2(rw[(k + 1) * D + c]);
#pragma unroll
        for (int p = 0; p < R2; ++p) {
            ulonglong2 x2 = *reinterpret_cast<const ulonglong2*>(&xs[p][2 * k]);
            fma2(acc[p], x2.x, w0);
            fma2(acc[p], x2.y, w1);
        }
    }
    // ---- z = x + mish(h) ----
#pragma unroll
    for (int p = 0; p < R2; ++p) {
        float h0, h1;
        unpack2(acc[p], h0, h1);
        zs[p][2 * c + 0] = xreg[2 * p + 0] + mishf(h0);
        zs[p][2 * c + 1] = xreg[2 * p + 1] + mishf(h1);
    }
    __syncthreads();

    // ---- out = z @ ow + ob ----
#pragma unroll
    for (int p = 0; p < R2; ++p) acc[p] = dup2(ob[c]);
#pragma unroll 4
    for (int k = 0; k < D; k += 2) {
        ull w0 = dup2(ow[(k + 0) * D + c]);
        ull w1 = dup2(ow[(k + 1) * D + c]);
#pragma unroll
        for (int p = 0; p < R2; ++p) {
            ulonglong2 z2 = *reinterpret_cast<const ulonglong2*>(&zs[p][2 * k]);
            fma2(acc[p], z2.x, w0);
            fma2(acc[p], z2.y, w1);
        }
    }

    // ---- store message rows at node-sorted slots (no atomics) ----
#pragma unroll
    for (int p = 0; p < R2; ++p) {
        float o0, o1;
        unpack2(acc[p], o0, o1);
        g_msg[(size_t)pos[2 * p + 0] * EDIM + e] = o0;
        g_msg[(size_t)pos[2 * p + 1] * EDIM + e] = o1;
    }
}

// ---------------- 7. segment reduce: max -> sum exp -> max_msg -------------
// One warp per node; lane handles columns (lane, lane+32).
__global__ void reduce_kernel() {
    int node = (blockIdx.x * blockDim.x + threadIdx.x) >> 5;
    if (node >= N_NODES) return;
    const int lane  = threadIdx.x & 31;
    const int start = g_start[node];
    const int end   = start + g_cnt[node];
    const float base = g_flag[node] ? -INFINITY : 0.0f;

    float m0 = base, m1 = base;
    for (int r = start; r < end; ++r) {
        const float* row = &g_msg[(size_t)r * EDIM];
        m0 = fmaxf(m0, row[lane]);
        m1 = fmaxf(m1, row[lane + 32]);
    }
    float s0 = 1e-16f, s1 = 1e-16f;
    for (int r = start; r < end; ++r) {
        const float* row = &g_msg[(size_t)r * EDIM];
        s0 += expf(12.0f * (row[lane]      - m0));
        s1 += expf(12.0f * (row[lane + 32] - m1));
    }
    size_t o = (size_t)node * EDIM;
    g_mf[o + lane]      = logf(s0) * (1.0f / 12.0f) + m0;
    g_mf[o + lane + 32] = logf(s1) * (1.0f / 12.0f) + m1;
}

// ---------------- 8. node update MLP: [max_msg | emb] (128) -> 64 ---------
template <int R>
__global__ void update_kernel(const float* __restrict__ emb,
                              const float* __restrict__ rw, const float* __restrict__ rb,
                              const float* __restrict__ ow, const float* __restrict__ ob,
                              float* __restrict__ out) {
    constexpr int R2 = R / 2;
    __shared__ __align__(16) float xs[R2][256];
    __shared__ __align__(16) float zs[R2][256];
    const int c  = threadIdx.x;     // 0..127
    const int n0 = blockIdx.x * R;

    float xreg[R];
#pragma unroll
    for (int r = 0; r < R; ++r) {
        int node = n0 + r;
        float v = (c < 64) ? g_mf[(size_t)node * EDIM + c]
                           : emb[(size_t)node * EDIM + (c - 64)];
        xreg[r] = v;
        xs[r >> 1][2 * c + (r & 1)] = v;
    }
    __syncthreads();

    ull acc[R2];
#pragma unroll
    for (int p = 0; p < R2; ++p) acc[p] = dup2(rb[c]);
#pragma unroll 4
    for (int k = 0; k < 128; k += 2) {
        ull w0 = dup2(rw[(k + 0) * 128 + c]);
        ull w1 = dup2(rw[(k + 1) * 128 + c]);
#pragma unroll
        for (int p = 0; p < R2; ++p) {
            ulonglong2 x2 = *reinterpret_cast<const ulonglong2*>(&xs[p][2 * k]);
            fma2(acc[p], x2.x, w0);
            fma2(acc[p], x2.y, w1);
        }
    }
#pragma unroll
    for (int p = 0; p < R2; ++p) {
        float h0, h1;
        unpack2(acc[p], h0, h1);
        zs[p][2 * c + 0] = xreg[2 * p + 0] + mishf(h0);
        zs[p][2 * c + 1] = xreg[2 * p + 1] + mishf(h1);
    }
    __syncthreads();

    const int cc = c & 63;
#pragma unroll
    for (int t = 0; t < 4; ++t) {
        int p = (c >> 6) + 2 * t;
        ull a = dup2(ob[cc]);
#pragma unroll 4
        for (int k = 0; k < 128; k += 2) {
            ull w0 = dup2(ow[(k + 0) * 64 + cc]);
            ull w1 = dup2(ow[(k + 1) * 64 + cc]);
            ulonglong2 z2 = *reinterpret_cast<const ulonglong2*>(&zs[p][2 * k]);
            fma2(a, z2.x, w0);
            fma2(a, z2.y, w1);
        }
        float o0, o1;
        unpack2(a, o0, o1);
        out[(size_t)(n0 + 2 * p + 0) * EDIM + cc] = o0;
        out[(size_t)(n0 + 2 * p + 1) * EDIM + cc] = o1;
    }
}

// ---------------- launcher ----------------
extern "C" void kernel_launch(void* const* d_in, const int* in_sizes, int n_in,
                              void* d_out, int out_size) {
    const float* emb = (const float*)d_in[0];
    const void*  i0  = d_in[1];
    const void*  i1  = d_in[2];
    const void*  i2  = d_in[3];
    const float* r0rw = (const float*)d_in[4];
    const float* r0rb = (const float*)d_in[5];
    const float* r0ow = (const float*)d_in[6];
    const float* r0ob = (const float*)d_in[7];
    const float* r1rw = (const float*)d_in[8];
    const float* r1rb = (const float*)d_in[9];
    const float* r1ow = (const float*)d_in[10];
    const float* r1ob = (const float*)d_in[11];
    const float* r2rw = (const float*)d_in[12];
    const float* r2rb = (const float*)d_in[13];
    const float* r2ow = (const float*)d_in[14];
    const float* r2ob = (const float*)d_in[15];
    const float* urw  = (const float*)d_in[16];
    const float* urb  = (const float*)d_in[17];
    const float* uow  = (const float*)d_in[18];
    const float* uob  = (const float*)d_in[19];
    float* out = (float*)d_out;

    // sort prelude
    detect_kernel<<<1, 256>>>((const unsigned*)i0);
    conv_kernel<<<(NROWS + 255) / 256, 256>>>(i0, i1, i2);
    hist_kernel<<<(NROWS + 255) / 256, 256>>>();
    scanA_kernel<<<SCAN_BLOCKS, 256>>>();
    scanB_kernel<<<1, SCAN_BLOCKS>>>();
    scanC_kernel<<<SCAN_BLOCKS, 256>>>();
    rank_kernel<<<(NROWS + 255) / 256, 256>>>();

    // messages
    msg_kernel<128, 2, 16><<<(L1 / 2) / 16, 128>>>(emb, r1rw, r1rb, r1ow, r1ob, L0);
    msg_kernel< 64, 1, 16><<<(L0 / 1) / 16,  64>>>(emb, r0rw, r0rb, r0ow, r0ob, 0);
    msg_kernel<192, 3, 16><<<(L2 / 3) / 16, 192>>>(emb, r2rw, r2rb, r2ow, r2ob, L0 + L1);

    // segment softmax-reduce, then node update
    reduce_kernel<<<(N_NODES * 32 + 255) / 256, 256>>>();
    update_kernel<16><<<N_NODES / 16, 128>>>(emb, urw, urb, uow, uob, out);
}